// round 8
// baseline (speedup 1.0000x reference)
#include <cuda_runtime.h>

// Shapes (fixed)
#define BB 256
#define NN 16
#define OBS 64
#define ACT 8
#define DD 128
#define HH 64
#define II 72
#define NF 192

// 16B-aligned padded strides (floats)
#define WE_S 76
#define W1_S 196
#define ST_S 68
#define AC_S 12
#define E_S  132
#define WT_S 17
#define HV_S 68

// float offsets into dynamic smem (all float4-aligned)
#define OFF_WEU 0
#define SZ_WEU  12544                 /* max(128*76=9728, 64*196=12544) */
#define OFF_WA  (OFF_WEU + SZ_WEU)
#define OFF_W2  (OFF_WA + 2 * DD)
#define OFF_ST  (OFF_W2 + HH)
#define OFF_AC  (OFF_ST + NN * ST_S)
#define OFF_PO  (OFF_AC + NN * AC_S)
#define OFF_TA  (OFF_PO + NN * AC_S)
#define OFF_DE  (OFF_TA + NN * E_S)
#define OFF_W   (OFF_DE + NN * E_S)
#define OFF_T   (OFF_W  + NN * WT_S)
#define OFF_V   (OFF_T  + NN * HV_S)
#define OFF_U   (OFF_V  + NN * HV_S)
#define OFF_SSRC (OFF_U + NN * HV_S)
#define OFF_SDST (OFF_SSRC + NN)
#define SMEM_FLOATS (OFF_SDST + NN)

__device__ __forceinline__ float lrelu(float x) {
    return fmaxf(x, 0.01f * x);
}

__device__ __forceinline__ float fast_tanh(float x) {
    float cx = fminf(fmaxf(x, -10.0f), 10.0f);
    float e = __expf(2.0f * cx);
    return __fdividef(e - 1.0f, e + 1.0f);
}

__device__ __forceinline__ float dot4(float4 a, float4 b, float acc) {
    acc = fmaf(a.x, b.x, acc);
    acc = fmaf(a.y, b.y, acc);
    acc = fmaf(a.z, b.z, acc);
    acc = fmaf(a.w, b.w, acc);
    return acc;
}

__global__ void __launch_bounds__(512, 2)
gac_kernel(const float* __restrict__ g_st, const float* __restrict__ g_po,
           const float* __restrict__ g_ac, const float* __restrict__ g_We,
           const float* __restrict__ g_Wa, const float* __restrict__ g_W1,
           const float* __restrict__ g_W2, float* __restrict__ out,
           int write_w)
{
    extern __shared__ float sm[];
    float* We  = sm + OFF_WEU;   // [128][76] phase 1
    float* W1  = sm + OFF_WEU;   // [64][196] phase 3+ (union)
    float* Wa  = sm + OFF_WA;
    float* W2s = sm + OFF_W2;
    float* st  = sm + OFF_ST;
    float* ac  = sm + OFF_AC;
    float* po  = sm + OFF_PO;
    float* ta  = sm + OFF_TA;
    float* de  = sm + OFF_DE;
    float* w   = sm + OFF_W;
    float* T   = sm + OFF_T;
    float* V   = sm + OFF_V;
    float* U   = sm + OFF_U;
    float* ssrc = sm + OFF_SSRC;
    float* sdst = sm + OFF_SDST;

    const int t = threadIdx.x;
    const int b = blockIdx.x;

    // ---- P0: cooperative float4 loads (512 threads) ----
    {
        // We: 128x72 = 2304 float4
        #pragma unroll
        for (int i = 0; i < 5; i++) {
            int idx = t + i * 512;
            if (idx < 2304) {
                int e = idx * 4;
                int r = e / II, c = e - r * II;
                *(float4*)&We[r * WE_S + c] = *(const float4*)&g_We[e];
            }
        }
        if (t < 64) *(float4*)&Wa[t * 4] = *(const float4*)&g_Wa[t * 4];
        if (t < 16) *(float4*)&W2s[t * 4] = *(const float4*)&g_W2[t * 4];
        if (t < 256) {
            int r = t >> 4, c = (t & 15) * 4;
            *(float4*)&st[r * ST_S + c] = *(const float4*)&g_st[b * NN * OBS + t * 4];
        }
        if (t < 32) {
            int r = t >> 1, c = (t & 1) * 4;
            *(float4*)&ac[r * AC_S + c] = *(const float4*)&g_ac[b * NN * ACT + t * 4];
            *(float4*)&po[r * AC_S + c] = *(const float4*)&g_po[b * NN * ACT + t * 4];
        }
        if (t < NN) { ssrc[t] = 0.0f; sdst[t] = 0.0f; }
    }
    __syncthreads();

    // ---- P1: embeddings, 1n x 4d tiles (16n x 32dq = 512 threads) ----
    {
        const int n = t & 15;
        const int d0 = (t >> 4) * 4;

        float sa[4], sp[4];
        #pragma unroll
        for (int u = 0; u < 4; u++) sa[u] = 0.0f;
        #pragma unroll
        for (int k = 0; k < OBS; k += 4) {
            float4 x = *(const float4*)&st[n * ST_S + k];
            #pragma unroll
            for (int u = 0; u < 4; u++) {
                float4 wv = *(const float4*)&We[(d0 + u) * WE_S + k];
                sa[u] = dot4(wv, x, sa[u]);
            }
        }
        #pragma unroll
        for (int u = 0; u < 4; u++) sp[u] = sa[u];
        #pragma unroll
        for (int k = 0; k < ACT; k += 4) {
            float4 xa = *(const float4*)&ac[n * AC_S + k];
            float4 xp = *(const float4*)&po[n * AC_S + k];
            #pragma unroll
            for (int u = 0; u < 4; u++) {
                float4 wv = *(const float4*)&We[(d0 + u) * WE_S + OBS + k];
                sa[u] = dot4(wv, xa, sa[u]);
                sp[u] = dot4(wv, xp, sp[u]);
            }
        }
        // attention-scalar partials for this (n, d-quad)
        float4 wsrc = *(const float4*)&Wa[d0];
        float4 wdst = *(const float4*)&Wa[DD + d0];
        float4 a0 = make_float4(sa[0], sa[1], sa[2], sa[3]);
        float psrc = dot4(wsrc, a0, 0.0f);
        float pdst = dot4(wdst, a0, 0.0f);
        // tanh + delta, float4 stores
        {
            float4 t0, dd0;
            t0.x = fast_tanh(sa[0]); t0.y = fast_tanh(sa[1]);
            t0.z = fast_tanh(sa[2]); t0.w = fast_tanh(sa[3]);
            dd0.x = fast_tanh(sp[0]) - t0.x; dd0.y = fast_tanh(sp[1]) - t0.y;
            dd0.z = fast_tanh(sp[2]) - t0.z; dd0.w = fast_tanh(sp[3]) - t0.w;
            *(float4*)&ta[n * E_S + d0] = t0;
            *(float4*)&de[n * E_S + d0] = dd0;
        }
        // lanes l and l^16 share n (t^16 flips a dq bit only)
        psrc += __shfl_xor_sync(0xffffffffu, psrc, 16);
        pdst += __shfl_xor_sync(0xffffffffu, pdst, 16);
        if ((t & 31) < 16) {
            atomicAdd(&ssrc[n], psrc);
            atomicAdd(&sdst[n], pdst);
        }
    }
    __syncthreads();

    // ---- P2: parallel softmax (t<256) + W1 float4 load (all 512) ----
    if (t < 256) {
        const int i = t >> 4, j = t & 15;
        float e = lrelu(ssrc[i] + sdst[j]);
        float mx = e;
        #pragma unroll
        for (int m = 8; m; m >>= 1)
            mx = fmaxf(mx, __shfl_xor_sync(0xffffffffu, mx, m));
        float ex = __expf(e - mx);
        float sum = ex;
        #pragma unroll
        for (int m = 8; m; m >>= 1)
            sum += __shfl_xor_sync(0xffffffffu, sum, m);
        float wv = __fdividef(ex, sum);
        w[i * WT_S + j] = wv;
        if (write_w)
            out[BB * NN * NN + b * NN * NN + t] = wv;
    }
    // W1: 64x192 = 3072 float4, 6 per thread (into union region)
    #pragma unroll
    for (int i = 0; i < 6; i++) {
        int e = (t + i * 512) * 4;
        int r = e / NF, c = e - r * NF;
        *(float4*)&W1[r * W1_S + c] = *(const float4*)&g_W1[e];
    }
    __syncthreads();

    // ---- P3: T[n,h]=(W1d.ta[n])/16, V[n,h]=(W1d.de[n])/16, au=W1s.st[n] ----
    // 16n x 32 h-pairs = 512 threads; au register-carried into P4a
    const int pn = t & 15, ph0 = (t >> 4) * 2;
    float au0 = 0.0f, au1 = 0.0f;
    {
        float at0 = 0.0f, at1 = 0.0f, av0 = 0.0f, av1 = 0.0f;
        #pragma unroll
        for (int k = 0; k < OBS; k += 4) {
            float4 x = *(const float4*)&st[pn * ST_S + k];
            float4 w0 = *(const float4*)&W1[(ph0 + 0) * W1_S + k];
            float4 w1 = *(const float4*)&W1[(ph0 + 1) * W1_S + k];
            au0 = dot4(w0, x, au0);
            au1 = dot4(w1, x, au1);
        }
        #pragma unroll
        for (int d = 0; d < DD; d += 4) {
            float4 xt = *(const float4*)&ta[pn * E_S + d];
            float4 xd = *(const float4*)&de[pn * E_S + d];
            float4 w0 = *(const float4*)&W1[(ph0 + 0) * W1_S + OBS + d];
            float4 w1 = *(const float4*)&W1[(ph0 + 1) * W1_S + OBS + d];
            at0 = dot4(w0, xt, at0);
            at1 = dot4(w1, xt, at1);
            av0 = dot4(w0, xd, av0);
            av1 = dot4(w1, xd, av1);
        }
        const float invN = 1.0f / 16.0f;
        float2 tv, vv;
        tv.x = at0 * invN; tv.y = at1 * invN;
        vv.x = av0 * invN; vv.y = av1 * invN;
        *(float2*)&T[pn * HV_S + ph0] = tv;
        *(float2*)&V[pn * HV_S + ph0] = vv;
    }
    __syncthreads();

    // ---- P4a: U[n,h] = au + sum_j w[n,j] * T[j,h]  (same mapping as P3) ----
    {
        float acc0 = au0, acc1 = au1;
        #pragma unroll
        for (int j = 0; j < NN; j++) {
            float wv = w[pn * WT_S + j];
            float2 tv = *(const float2*)&T[j * HV_S + ph0];
            acc0 = fmaf(wv, tv.x, acc0);
            acc1 = fmaf(wv, tv.y, acc1);
        }
        float2 uv; uv.x = acc0; uv.y = acc1;
        *(float2*)&U[pn * HV_S + ph0] = uv;
    }
    __syncthreads();

    // ---- P4b: value[b,i,j] = W2 . lrelu(U[i] + w[i,j]*V[j]) ----
    // 256 (i,j) pairs x 2 h-halves; combine via shfl_xor(1)
    {
        const int p = t >> 1, half = t & 1;
        const int i = p >> 4, j = p & 15;
        const int hb = half * 32;
        float wv = w[i * WT_S + j];
        float acc = 0.0f;
        #pragma unroll
        for (int h = 0; h < 32; h += 4) {
            float4 u4 = *(const float4*)&U[i * HV_S + hb + h];
            float4 v4 = *(const float4*)&V[j * HV_S + hb + h];
            float4 w2 = *(const float4*)&W2s[hb + h];
            acc = fmaf(w2.x, lrelu(fmaf(wv, v4.x, u4.x)), acc);
            acc = fmaf(w2.y, lrelu(fmaf(wv, v4.y, u4.y)), acc);
            acc = fmaf(w2.z, lrelu(fmaf(wv, v4.z, u4.z)), acc);
            acc = fmaf(w2.w, lrelu(fmaf(wv, v4.w, u4.w)), acc);
        }
        acc += __shfl_xor_sync(0xffffffffu, acc, 1);
        if (half == 0)
            out[b * NN * NN + p] = acc;
    }
}

extern "C" void kernel_launch(void* const* d_in, const int* in_sizes, int n_in,
                              void* d_out, int out_size) {
    const float* st = (const float*)d_in[0];
    const float* po = (const float*)d_in[1];
    const float* ac = (const float*)d_in[2];
    const float* We = (const float*)d_in[3];
    const float* Wa = (const float*)d_in[4];
    const float* W1 = (const float*)d_in[5];
    const float* W2 = (const float*)d_in[6];
    float* out = (float*)d_out;

    const int smem = SMEM_FLOATS * (int)sizeof(float);
    cudaFuncSetAttribute(gac_kernel, cudaFuncAttributeMaxDynamicSharedMemorySize, smem);

    int write_w = (out_size >= 2 * BB * NN * NN) ? 1 : 0;

    gac_kernel<<<BB, 512, smem>>>(st, po, ac, We, Wa, W1, W2, out, write_w);
}

// round 9
// speedup vs baseline: 1.0111x; 1.0111x over previous
#include <cuda_runtime.h>

// Shapes (fixed)
#define BB 256
#define NN 16
#define OBS 64
#define ACT 8
#define DD 128
#define HH 64
#define II 72
#define NF 192

// 16B-aligned padded strides (floats)
#define WE_S 76
#define W1_S 196
#define ST_S 68
#define AC_S 12
#define E_S  132
#define WT_S 17
#define HV_S 68

// float offsets into dynamic smem (all float4-aligned)
#define OFF_WEU 0
#define SZ_WEU  12544                 /* max(128*76=9728, 64*196=12544) */
#define OFF_WA  (OFF_WEU + SZ_WEU)
#define OFF_W2  (OFF_WA + 2 * DD)
#define OFF_ST  (OFF_W2 + HH)
#define OFF_AC  (OFF_ST + NN * ST_S)
#define OFF_PO  (OFF_AC + NN * AC_S)
#define OFF_TA  (OFF_PO + NN * AC_S)
#define OFF_DE  (OFF_TA + NN * E_S)
#define OFF_W   (OFF_DE + NN * E_S)
#define OFF_T   (OFF_W  + NN * WT_S)
#define OFF_V   (OFF_T  + NN * HV_S)
#define OFF_U   (OFF_V  + NN * HV_S)
#define OFF_SSRC (OFF_U + NN * HV_S)
#define OFF_SDST (OFF_SSRC + NN)
#define SMEM_FLOATS (OFF_SDST + NN)

__device__ __forceinline__ float lrelu(float x) {
    return fmaxf(x, 0.01f * x);
}

__device__ __forceinline__ float fast_tanh(float x) {
    float cx = fminf(fmaxf(x, -10.0f), 10.0f);
    float e = __expf(2.0f * cx);
    return __fdividef(e - 1.0f, e + 1.0f);
}

__device__ __forceinline__ float dot4(float4 a, float4 b, float acc) {
    acc = fmaf(a.x, b.x, acc);
    acc = fmaf(a.y, b.y, acc);
    acc = fmaf(a.z, b.z, acc);
    acc = fmaf(a.w, b.w, acc);
    return acc;
}

__global__ void __launch_bounds__(512, 2)
gac_kernel(const float* __restrict__ g_st, const float* __restrict__ g_po,
           const float* __restrict__ g_ac, const float* __restrict__ g_We,
           const float* __restrict__ g_Wa, const float* __restrict__ g_W1,
           const float* __restrict__ g_W2, float* __restrict__ out,
           int write_w)
{
    extern __shared__ float sm[];
    float* We  = sm + OFF_WEU;   // [128][76] phase 1
    float* W1  = sm + OFF_WEU;   // [64][196] phase 3+ (union)
    float* Wa  = sm + OFF_WA;
    float* W2s = sm + OFF_W2;
    float* st  = sm + OFF_ST;
    float* ac  = sm + OFF_AC;
    float* po  = sm + OFF_PO;
    float* ta  = sm + OFF_TA;
    float* de  = sm + OFF_DE;
    float* w   = sm + OFF_W;
    float* T   = sm + OFF_T;
    float* V   = sm + OFF_V;
    float* U   = sm + OFF_U;
    float* ssrc = sm + OFF_SSRC;
    float* sdst = sm + OFF_SDST;

    const int t = threadIdx.x;
    const int b = blockIdx.x;

    // ---- P0: cooperative float4 loads (512 threads) ----
    {
        #pragma unroll
        for (int i = 0; i < 5; i++) {
            int idx = t + i * 512;
            if (idx < 2304) {
                int e = idx * 4;
                int r = e / II, c = e - r * II;
                *(float4*)&We[r * WE_S + c] = *(const float4*)&g_We[e];
            }
        }
        if (t < 64) *(float4*)&Wa[t * 4] = *(const float4*)&g_Wa[t * 4];
        if (t < 16) *(float4*)&W2s[t * 4] = *(const float4*)&g_W2[t * 4];
        if (t < 256) {
            int r = t >> 4, c = (t & 15) * 4;
            *(float4*)&st[r * ST_S + c] = *(const float4*)&g_st[b * NN * OBS + t * 4];
        }
        if (t < 32) {
            int r = t >> 1, c = (t & 1) * 4;
            *(float4*)&ac[r * AC_S + c] = *(const float4*)&g_ac[b * NN * ACT + t * 4];
            *(float4*)&po[r * AC_S + c] = *(const float4*)&g_po[b * NN * ACT + t * 4];
        }
        if (t < NN) { ssrc[t] = 0.0f; sdst[t] = 0.0f; }
    }
    __syncthreads();

    // ---- P1: embeddings, 2n x 4d tiles, split-K over kh = lane bit 3 ----
    {
        const int np = t & 7;
        const int n0 = np * 2, n1 = n0 + 1;
        const int kh = (t >> 3) & 1;       // K-half (intra-warp)
        const int d0 = (t >> 4) * 4;       // d-quad 0..31

        float sa0[4], sa1[4], sp0[4], sp1[4];
        #pragma unroll
        for (int u = 0; u < 4; u++) { sa0[u] = 0.0f; sa1[u] = 0.0f; sp0[u] = 0.0f; sp1[u] = 0.0f; }
        // OBS half: k in [kh*32, kh*32+32)
        const int kb = kh * 32;
        #pragma unroll
        for (int kk = 0; kk < 32; kk += 4) {
            int k = kb + kk;
            float4 x0 = *(const float4*)&st[n0 * ST_S + k];
            float4 x1 = *(const float4*)&st[n1 * ST_S + k];
            #pragma unroll
            for (int u = 0; u < 4; u++) {
                float4 wv = *(const float4*)&We[(d0 + u) * WE_S + k];
                sa0[u] = dot4(wv, x0, sa0[u]);
                sa1[u] = dot4(wv, x1, sa1[u]);
            }
        }
        // ACT half: one k-quad at 64 + kh*4 (obs part of sp == sa handled after combine? no:
        // sp accumulates only ACT-dependent diff? Careful: sp must equal full emb_p.
        // emb_p = W*obs + W*po ; emb_a = W*obs + W*ac. Accumulate obs part into sa only,
        // and track ACT parts separately so sp = sa_obs + act_p. Do: sp holds only
        // (W*po - handled via separate acc), then sp_final = (sa_obs) + act_p.
        // Simplest correct: accumulate act_a into sa, act_p into sp; after the kh-combine,
        // sp += (sa - act_a_combined)?  Instead: keep obs sum in sa only; store act sums:
        {
            int kq = 64 + kh * 4;
            float4 xa0 = *(const float4*)&ac[n0 * AC_S + kh * 4];
            float4 xa1 = *(const float4*)&ac[n1 * AC_S + kh * 4];
            float4 xp0 = *(const float4*)&po[n0 * AC_S + kh * 4];
            float4 xp1 = *(const float4*)&po[n1 * AC_S + kh * 4];
            #pragma unroll
            for (int u = 0; u < 4; u++) {
                float4 wv = *(const float4*)&We[(d0 + u) * WE_S + kq];
                float a0v = dot4(wv, xa0, 0.0f);
                float a1v = dot4(wv, xa1, 0.0f);
                float p0v = dot4(wv, xp0, 0.0f);
                float p1v = dot4(wv, xp1, 0.0f);
                // sp currently tracks (emb_p - emb_a) partial; sa tracks emb_a partial
                sa0[u] += a0v; sp0[u] += p0v - a0v;
                sa1[u] += a1v; sp1[u] += p1v - a1v;
            }
        }
        // combine K-halves across kh (lane bit 3)
        #pragma unroll
        for (int u = 0; u < 4; u++) {
            sa0[u] += __shfl_xor_sync(0xffffffffu, sa0[u], 8);
            sa1[u] += __shfl_xor_sync(0xffffffffu, sa1[u], 8);
            sp0[u] += __shfl_xor_sync(0xffffffffu, sp0[u], 8);
            sp1[u] += __shfl_xor_sync(0xffffffffu, sp1[u], 8);
        }
        // now sa = emb_a (full), sp = emb_p - emb_a (full) on both kh lanes
        // attention-scalar partials (computed once per kh pair: kh==0 lanes)
        float4 wsrc = *(const float4*)&Wa[d0];
        float4 wdst = *(const float4*)&Wa[DD + d0];
        float4 a0 = make_float4(sa0[0], sa0[1], sa0[2], sa0[3]);
        float4 a1 = make_float4(sa1[0], sa1[1], sa1[2], sa1[3]);
        float ps0 = dot4(wsrc, a0, 0.0f), ps1 = dot4(wsrc, a1, 0.0f);
        float pd0 = dot4(wdst, a0, 0.0f), pd1 = dot4(wdst, a1, 0.0f);
        // reduce over d-quads: lanes sharing (np, kh): xor 16 only (bit4 = dq low bit)
        ps0 += __shfl_xor_sync(0xffffffffu, ps0, 16);
        ps1 += __shfl_xor_sync(0xffffffffu, ps1, 16);
        pd0 += __shfl_xor_sync(0xffffffffu, pd0, 16);
        pd1 += __shfl_xor_sync(0xffffffffu, pd1, 16);
        if ((t & 31) < 8) {   // np 0..7, kh=0, dq-even: one lane per (warp, np)
            atomicAdd(&ssrc[n0], ps0);
            atomicAdd(&ssrc[n1], ps1);
            atomicAdd(&sdst[n0], pd0);
            atomicAdd(&sdst[n1], pd1);
        }
        // tanh + delta stores (kh==0 lanes only)
        if (kh == 0) {
            float4 t0, t1, dd0, dd1;
            t0.x = fast_tanh(sa0[0]); t0.y = fast_tanh(sa0[1]);
            t0.z = fast_tanh(sa0[2]); t0.w = fast_tanh(sa0[3]);
            t1.x = fast_tanh(sa1[0]); t1.y = fast_tanh(sa1[1]);
            t1.z = fast_tanh(sa1[2]); t1.w = fast_tanh(sa1[3]);
            dd0.x = fast_tanh(sa0[0] + sp0[0]) - t0.x;
            dd0.y = fast_tanh(sa0[1] + sp0[1]) - t0.y;
            dd0.z = fast_tanh(sa0[2] + sp0[2]) - t0.z;
            dd0.w = fast_tanh(sa0[3] + sp0[3]) - t0.w;
            dd1.x = fast_tanh(sa1[0] + sp1[0]) - t1.x;
            dd1.y = fast_tanh(sa1[1] + sp1[1]) - t1.y;
            dd1.z = fast_tanh(sa1[2] + sp1[2]) - t1.z;
            dd1.w = fast_tanh(sa1[3] + sp1[3]) - t1.w;
            *(float4*)&ta[n0 * E_S + d0] = t0;
            *(float4*)&ta[n1 * E_S + d0] = t1;
            *(float4*)&de[n0 * E_S + d0] = dd0;
            *(float4*)&de[n1 * E_S + d0] = dd1;
        }
    }
    __syncthreads();

    // ---- P2: parallel softmax (t<256) + W1 float4 load (all 512) ----
    if (t < 256) {
        const int i = t >> 4, j = t & 15;
        float e = lrelu(ssrc[i] + sdst[j]);
        float mx = e;
        #pragma unroll
        for (int m = 8; m; m >>= 1)
            mx = fmaxf(mx, __shfl_xor_sync(0xffffffffu, mx, m));
        float ex = __expf(e - mx);
        float sum = ex;
        #pragma unroll
        for (int m = 8; m; m >>= 1)
            sum += __shfl_xor_sync(0xffffffffu, sum, m);
        float wv = __fdividef(ex, sum);
        w[i * WT_S + j] = wv;
        if (write_w)
            out[BB * NN * NN + b * NN * NN + t] = wv;
    }
    #pragma unroll
    for (int i = 0; i < 6; i++) {
        int e = (t + i * 512) * 4;
        int r = e / NF, c = e - r * NF;
        *(float4*)&W1[r * W1_S + c] = *(const float4*)&g_W1[e];
    }
    __syncthreads();

    // ---- P3: 4h x 1n tiles, split-K over kh = lane bit 4 ----
    const int pn = t & 15;
    const int pkh = (t >> 4) & 1;
    const int ph0 = (t >> 5) * 4;      // h-quad 0..15
    float auf[4];
    {
        float at[4], av[4];
        #pragma unroll
        for (int u = 0; u < 4; u++) { at[u] = 0.0f; av[u] = 0.0f; auf[u] = 0.0f; }
        // OBS half: k in [pkh*32, pkh*32+32)
        const int kb = pkh * 32;
        #pragma unroll
        for (int kk = 0; kk < 32; kk += 4) {
            int k = kb + kk;
            float4 x = *(const float4*)&st[pn * ST_S + k];
            #pragma unroll
            for (int u = 0; u < 4; u++) {
                float4 wv = *(const float4*)&W1[(ph0 + u) * W1_S + k];
                auf[u] = dot4(wv, x, auf[u]);
            }
        }
        // DD half: d in [pkh*64, pkh*64+64)
        const int db = pkh * 64;
        #pragma unroll
        for (int dd = 0; dd < 64; dd += 4) {
            int d = db + dd;
            float4 xt = *(const float4*)&ta[pn * E_S + d];
            float4 xd = *(const float4*)&de[pn * E_S + d];
            #pragma unroll
            for (int u = 0; u < 4; u++) {
                float4 wv = *(const float4*)&W1[(ph0 + u) * W1_S + OBS + d];
                at[u] = dot4(wv, xt, at[u]);
                av[u] = dot4(wv, xd, av[u]);
            }
        }
        // combine K-halves (lane bit 4)
        #pragma unroll
        for (int u = 0; u < 4; u++) {
            at[u] += __shfl_xor_sync(0xffffffffu, at[u], 16);
            av[u] += __shfl_xor_sync(0xffffffffu, av[u], 16);
            auf[u] += __shfl_xor_sync(0xffffffffu, auf[u], 16);
        }
        if (pkh == 0) {
            const float invN = 1.0f / 16.0f;
            float4 tv, vv;
            tv.x = at[0] * invN; tv.y = at[1] * invN;
            tv.z = at[2] * invN; tv.w = at[3] * invN;
            vv.x = av[0] * invN; vv.y = av[1] * invN;
            vv.z = av[2] * invN; vv.w = av[3] * invN;
            *(float4*)&T[pn * HV_S + ph0] = tv;
            *(float4*)&V[pn * HV_S + ph0] = vv;
        }
    }
    __syncthreads();

    // ---- P4a: U[n,h] = au + sum_j w[n,j]*T[j,h], split j over pkh ----
    {
        float acc[4];
        #pragma unroll
        for (int u = 0; u < 4; u++) acc[u] = (pkh == 0) ? auf[u] : 0.0f;
        const int jb = pkh * 8;
        #pragma unroll
        for (int jj = 0; jj < 8; jj++) {
            int j = jb + jj;
            float wv = w[pn * WT_S + j];
            float4 tv = *(const float4*)&T[j * HV_S + ph0];
            acc[0] = fmaf(wv, tv.x, acc[0]);
            acc[1] = fmaf(wv, tv.y, acc[1]);
            acc[2] = fmaf(wv, tv.z, acc[2]);
            acc[3] = fmaf(wv, tv.w, acc[3]);
        }
        #pragma unroll
        for (int u = 0; u < 4; u++)
            acc[u] += __shfl_xor_sync(0xffffffffu, acc[u], 16);
        if (pkh == 0) {
            float4 uv;
            uv.x = acc[0]; uv.y = acc[1]; uv.z = acc[2]; uv.w = acc[3];
            *(float4*)&U[pn * HV_S + ph0] = uv;
        }
    }
    __syncthreads();

    // ---- P4b: value[b,i,j] = W2 . lrelu(U[i] + w[i,j]*V[j]) ----
    // 256 (i,j) pairs x 2 h-halves; combine via shfl_xor(1)
    {
        const int p = t >> 1, half = t & 1;
        const int i = p >> 4, j = p & 15;
        const int hb = half * 32;
        float wv = w[i * WT_S + j];
        float acc = 0.0f;
        #pragma unroll
        for (int h = 0; h < 32; h += 4) {
            float4 u4 = *(const float4*)&U[i * HV_S + hb + h];
            float4 v4 = *(const float4*)&V[j * HV_S + hb + h];
            float4 w2 = *(const float4*)&W2s[hb + h];
            acc = fmaf(w2.x, lrelu(fmaf(wv, v4.x, u4.x)), acc);
            acc = fmaf(w2.y, lrelu(fmaf(wv, v4.y, u4.y)), acc);
            acc = fmaf(w2.z, lrelu(fmaf(wv, v4.z, u4.z)), acc);
            acc = fmaf(w2.w, lrelu(fmaf(wv, v4.w, u4.w)), acc);
        }
        acc += __shfl_xor_sync(0xffffffffu, acc, 1);
        if (half == 0)
            out[b * NN * NN + p] = acc;
    }
}

extern "C" void kernel_launch(void* const* d_in, const int* in_sizes, int n_in,
                              void* d_out, int out_size) {
    const float* st = (const float*)d_in[0];
    const float* po = (const float*)d_in[1];
    const float* ac = (const float*)d_in[2];
    const float* We = (const float*)d_in[3];
    const float* Wa = (const float*)d_in[4];
    const float* W1 = (const float*)d_in[5];
    const float* W2 = (const float*)d_in[6];
    float* out = (float*)d_out;

    const int smem = SMEM_FLOATS * (int)sizeof(float);
    cudaFuncSetAttribute(gac_kernel, cudaFuncAttributeMaxDynamicSharedMemorySize, smem);

    int write_w = (out_size >= 2 * BB * NN * NN) ? 1 : 0;

    gac_kernel<<<BB, 512, smem>>>(st, po, ac, We, Wa, W1, W2, out, write_w);
}

// round 11
// speedup vs baseline: 1.3814x; 1.3662x over previous
#include <cuda_runtime.h>

// Shapes (fixed)
#define BB 256
#define NN 16
#define OBS 64
#define ACT 8
#define DD 128
#define HH 64
#define II 72
#define NF 192

// 16B-aligned padded strides (floats)
#define WE_S 76
#define W1_S 196
#define ST_S 68
#define AC_S 12
#define E_S  132
#define WT_S 17
#define HV_S 68

// bank swizzle: rows n>=8 get their column-quads XOR'd by 4 words (16B)
#define SW(n) (((n) & 8) >> 1)

// float offsets into dynamic smem (all float4-aligned)
#define OFF_WEU 0
#define SZ_WEU  12544                 /* max(128*76=9728, 64*196=12544) */
#define OFF_WA  (OFF_WEU + SZ_WEU)
#define OFF_W2  (OFF_WA + 2 * DD)
#define OFF_ST  (OFF_W2 + HH)
#define OFF_AC  (OFF_ST + NN * ST_S)
#define OFF_PO  (OFF_AC + NN * AC_S)
#define OFF_TA  (OFF_PO + NN * AC_S)
#define OFF_DE  (OFF_TA + NN * E_S)
#define OFF_W   (OFF_DE + NN * E_S)
#define OFF_T1  (OFF_W  + NN * WT_S)
#define OFF_V1  (OFF_T1 + NN * HV_S)
#define OFF_U   (OFF_V1 + NN * HV_S)
#define OFF_T2  (OFF_U  + NN * HV_S)
#define OFF_V2  (OFF_T2 + NN * HV_S)
#define OFF_SSRC (OFF_V2 + NN * HV_S)
#define OFF_SDST (OFF_SSRC + NN)
#define SMEM_FLOATS (OFF_SDST + NN)

__device__ __forceinline__ float lrelu(float x) {
    return fmaxf(x, 0.01f * x);
}

__device__ __forceinline__ float fast_tanh(float x) {
    float cx = fminf(fmaxf(x, -10.0f), 10.0f);
    float e = __expf(2.0f * cx);
    return __fdividef(e - 1.0f, e + 1.0f);
}

__device__ __forceinline__ float dot4(float4 a, float4 b, float acc) {
    acc = fmaf(a.x, b.x, acc);
    acc = fmaf(a.y, b.y, acc);
    acc = fmaf(a.z, b.z, acc);
    acc = fmaf(a.w, b.w, acc);
    return acc;
}

__global__ void __launch_bounds__(256, 2)
gac_kernel(const float* __restrict__ g_st, const float* __restrict__ g_po,
           const float* __restrict__ g_ac, const float* __restrict__ g_We,
           const float* __restrict__ g_Wa, const float* __restrict__ g_W1,
           const float* __restrict__ g_W2, float* __restrict__ out,
           int write_w)
{
    extern __shared__ float sm[];
    float* We  = sm + OFF_WEU;   // [128][76] phase 1
    float* W1  = sm + OFF_WEU;   // [64][196] phase 3+ (union)
    float* Wa  = sm + OFF_WA;
    float* W2s = sm + OFF_W2;
    float* st  = sm + OFF_ST;
    float* ac  = sm + OFF_AC;
    float* po  = sm + OFF_PO;
    float* ta  = sm + OFF_TA;
    float* de  = sm + OFF_DE;
    float* w   = sm + OFF_W;
    float* T1  = sm + OFF_T1;
    float* V1  = sm + OFF_V1;
    float* U   = sm + OFF_U;
    float* T2  = sm + OFF_T2;
    float* V2  = sm + OFF_V2;
    float* ssrc = sm + OFF_SSRC;
    float* sdst = sm + OFF_SDST;

    const int t = threadIdx.x;
    const int b = blockIdx.x;

    // ---- P0: cooperative float4 loads ----
    {
        #pragma unroll
        for (int i = 0; i < 9; i++) {
            int e = (t + i * 256) * 4;
            int r = e / II, c = e - r * II;
            *(float4*)&We[r * WE_S + c] = *(const float4*)&g_We[e];
        }
        if (t < 64) *(float4*)&Wa[t * 4] = *(const float4*)&g_Wa[t * 4];
        if (t < 16) *(float4*)&W2s[t * 4] = *(const float4*)&g_W2[t * 4];
        {
            int r = t >> 4, c = (t & 15) * 4;
            *(float4*)&st[r * ST_S + (c ^ SW(r))] = *(const float4*)&g_st[b * NN * OBS + t * 4];
        }
        if (t < 32) {
            int r = t >> 1, c = (t & 1) * 4;
            *(float4*)&ac[r * AC_S + c] = *(const float4*)&g_ac[b * NN * ACT + t * 4];
            *(float4*)&po[r * AC_S + c] = *(const float4*)&g_po[b * NN * ACT + t * 4];
        }
        if (t < NN) { ssrc[t] = 0.0f; sdst[t] = 0.0f; }
    }
    __syncthreads();

    // ---- P1: embeddings, 2n x 4d tiles (np = t&7, d-quad = t>>3) ----
    {
        const int np = t & 7;
        const int n0 = np * 2, n1 = n0 + 1;
        const int d0 = (t >> 3) * 4;           // FIXED: 32 d-quads, full D=128
        const int sw = SW(n0);

        float sa0[4], sa1[4], sp0[4], sp1[4];
        #pragma unroll
        for (int u = 0; u < 4; u++) { sa0[u] = 0.0f; sa1[u] = 0.0f; }
        #pragma unroll
        for (int k = 0; k < OBS; k += 4) {
            float4 x0 = *(const float4*)&st[n0 * ST_S + (k ^ sw)];
            float4 x1 = *(const float4*)&st[n1 * ST_S + (k ^ sw)];
            #pragma unroll
            for (int u = 0; u < 4; u++) {
                float4 wv = *(const float4*)&We[(d0 + u) * WE_S + k];
                sa0[u] = dot4(wv, x0, sa0[u]);
                sa1[u] = dot4(wv, x1, sa1[u]);
            }
        }
        #pragma unroll
        for (int u = 0; u < 4; u++) { sp0[u] = sa0[u]; sp1[u] = sa1[u]; }
        #pragma unroll
        for (int k = 0; k < ACT; k += 4) {
            float4 xa0 = *(const float4*)&ac[n0 * AC_S + k];
            float4 xa1 = *(const float4*)&ac[n1 * AC_S + k];
            float4 xp0 = *(const float4*)&po[n0 * AC_S + k];
            float4 xp1 = *(const float4*)&po[n1 * AC_S + k];
            #pragma unroll
            for (int u = 0; u < 4; u++) {
                float4 wv = *(const float4*)&We[(d0 + u) * WE_S + OBS + k];
                sa0[u] = dot4(wv, xa0, sa0[u]);
                sa1[u] = dot4(wv, xa1, sa1[u]);
                sp0[u] = dot4(wv, xp0, sp0[u]);
                sp1[u] = dot4(wv, xp1, sp1[u]);
            }
        }
        // attention-scalar partials
        float4 wsrc = *(const float4*)&Wa[d0];
        float4 wdst = *(const float4*)&Wa[DD + d0];
        float4 a0 = make_float4(sa0[0], sa0[1], sa0[2], sa0[3]);
        float4 a1 = make_float4(sa1[0], sa1[1], sa1[2], sa1[3]);
        float ps0 = dot4(wsrc, a0, 0.0f), ps1 = dot4(wsrc, a1, 0.0f);
        float pd0 = dot4(wdst, a0, 0.0f), pd1 = dot4(wdst, a1, 0.0f);
        // tanh + delta, float4 swizzled stores
        {
            float4 t0, t1, dd0, dd1;
            t0.x = fast_tanh(sa0[0]); t0.y = fast_tanh(sa0[1]);
            t0.z = fast_tanh(sa0[2]); t0.w = fast_tanh(sa0[3]);
            t1.x = fast_tanh(sa1[0]); t1.y = fast_tanh(sa1[1]);
            t1.z = fast_tanh(sa1[2]); t1.w = fast_tanh(sa1[3]);
            dd0.x = fast_tanh(sp0[0]) - t0.x; dd0.y = fast_tanh(sp0[1]) - t0.y;
            dd0.z = fast_tanh(sp0[2]) - t0.z; dd0.w = fast_tanh(sp0[3]) - t0.w;
            dd1.x = fast_tanh(sp1[0]) - t1.x; dd1.y = fast_tanh(sp1[1]) - t1.y;
            dd1.z = fast_tanh(sp1[2]) - t1.z; dd1.w = fast_tanh(sp1[3]) - t1.w;
            *(float4*)&ta[n0 * E_S + (d0 ^ sw)] = t0;
            *(float4*)&ta[n1 * E_S + (d0 ^ sw)] = t1;
            *(float4*)&de[n0 * E_S + (d0 ^ sw)] = dd0;
            *(float4*)&de[n1 * E_S + (d0 ^ sw)] = dd1;
        }
        // reduce partials over the 4 lanes sharing np (lane bits 3,4 = d-quad low bits)
        ps0 += __shfl_xor_sync(0xffffffffu, ps0, 8);
        ps0 += __shfl_xor_sync(0xffffffffu, ps0, 16);
        ps1 += __shfl_xor_sync(0xffffffffu, ps1, 8);
        ps1 += __shfl_xor_sync(0xffffffffu, ps1, 16);
        pd0 += __shfl_xor_sync(0xffffffffu, pd0, 8);
        pd0 += __shfl_xor_sync(0xffffffffu, pd0, 16);
        pd1 += __shfl_xor_sync(0xffffffffu, pd1, 8);
        pd1 += __shfl_xor_sync(0xffffffffu, pd1, 16);
        if ((t & 31) < 8) {
            atomicAdd(&ssrc[n0], ps0);
            atomicAdd(&ssrc[n1], ps1);
            atomicAdd(&sdst[n0], pd0);
            atomicAdd(&sdst[n1], pd1);
        }
    }
    __syncthreads();

    // ---- P2: parallel softmax + W1 float4 load ----
    {
        const int i = t >> 4, j = t & 15;
        float e = lrelu(ssrc[i] + sdst[j]);
        float mx = e;
        #pragma unroll
        for (int m = 8; m; m >>= 1)
            mx = fmaxf(mx, __shfl_xor_sync(0xffffffffu, mx, m));
        float ex = __expf(e - mx);
        float sum = ex;
        #pragma unroll
        for (int m = 8; m; m >>= 1)
            sum += __shfl_xor_sync(0xffffffffu, sum, m);
        float wv = __fdividef(ex, sum);
        w[i * WT_S + j] = wv * 0.0625f;   // store w/16; T,V stay unscaled
        if (write_w)
            out[BB * NN * NN + b * NN * NN + t] = wv;
    }
    #pragma unroll
    for (int i = 0; i < 12; i++) {
        int e = (t + i * 256) * 4;
        int r = e / NF, c = e - r * NF;
        *(float4*)&W1[r * W1_S + c] = *(const float4*)&g_W1[e];
    }
    __syncthreads();

    // ---- P3: split-K, 2n x 4h tiles ----
    // group A (t<128): au over OBS + T/V partials over d in [0,48)
    // group B (t>=128): T/V partials over d in [48,128)
    {
        const int np = t & 7;
        const int n0 = np * 2, n1 = n0 + 1;
        const int h0 = ((t >> 3) & 15) * 4;
        const int sw = SW(n0);

        float at0[4], at1[4], av0[4], av1[4];
        #pragma unroll
        for (int u = 0; u < 4; u++) { at0[u] = 0.0f; at1[u] = 0.0f; av0[u] = 0.0f; av1[u] = 0.0f; }

        if (t < 128) {
            float au0[4], au1[4];
            #pragma unroll
            for (int u = 0; u < 4; u++) { au0[u] = 0.0f; au1[u] = 0.0f; }
            #pragma unroll
            for (int k = 0; k < OBS; k += 4) {
                float4 x0 = *(const float4*)&st[n0 * ST_S + (k ^ sw)];
                float4 x1 = *(const float4*)&st[n1 * ST_S + (k ^ sw)];
                #pragma unroll
                for (int u = 0; u < 4; u++) {
                    float4 wv = *(const float4*)&W1[(h0 + u) * W1_S + k];
                    au0[u] = dot4(wv, x0, au0[u]);
                    au1[u] = dot4(wv, x1, au1[u]);
                }
            }
            #pragma unroll
            for (int d = 0; d < 48; d += 4) {
                float4 xt0 = *(const float4*)&ta[n0 * E_S + (d ^ sw)];
                float4 xt1 = *(const float4*)&ta[n1 * E_S + (d ^ sw)];
                float4 xd0 = *(const float4*)&de[n0 * E_S + (d ^ sw)];
                float4 xd1 = *(const float4*)&de[n1 * E_S + (d ^ sw)];
                #pragma unroll
                for (int u = 0; u < 4; u++) {
                    float4 wv = *(const float4*)&W1[(h0 + u) * W1_S + OBS + d];
                    at0[u] = dot4(wv, xt0, at0[u]);
                    at1[u] = dot4(wv, xt1, at1[u]);
                    av0[u] = dot4(wv, xd0, av0[u]);
                    av1[u] = dot4(wv, xd1, av1[u]);
                }
            }
            float4 f;
            f.x = au0[0]; f.y = au0[1]; f.z = au0[2]; f.w = au0[3];
            *(float4*)&U[n0 * HV_S + h0] = f;
            f.x = au1[0]; f.y = au1[1]; f.z = au1[2]; f.w = au1[3];
            *(float4*)&U[n1 * HV_S + h0] = f;
            f.x = at0[0]; f.y = at0[1]; f.z = at0[2]; f.w = at0[3];
            *(float4*)&T1[n0 * HV_S + h0] = f;
            f.x = at1[0]; f.y = at1[1]; f.z = at1[2]; f.w = at1[3];
            *(float4*)&T1[n1 * HV_S + h0] = f;
            f.x = av0[0]; f.y = av0[1]; f.z = av0[2]; f.w = av0[3];
            *(float4*)&V1[n0 * HV_S + h0] = f;
            f.x = av1[0]; f.y = av1[1]; f.z = av1[2]; f.w = av1[3];
            *(float4*)&V1[n1 * HV_S + h0] = f;
        } else {
            #pragma unroll
            for (int d = 48; d < DD; d += 4) {
                float4 xt0 = *(const float4*)&ta[n0 * E_S + (d ^ sw)];
                float4 xt1 = *(const float4*)&ta[n1 * E_S + (d ^ sw)];
                float4 xd0 = *(const float4*)&de[n0 * E_S + (d ^ sw)];
                float4 xd1 = *(const float4*)&de[n1 * E_S + (d ^ sw)];
                #pragma unroll
                for (int u = 0; u < 4; u++) {
                    float4 wv = *(const float4*)&W1[(h0 + u) * W1_S + OBS + d];
                    at0[u] = dot4(wv, xt0, at0[u]);
                    at1[u] = dot4(wv, xt1, at1[u]);
                    av0[u] = dot4(wv, xd0, av0[u]);
                    av1[u] = dot4(wv, xd1, av1[u]);
                }
            }
            float4 f;
            f.x = at0[0]; f.y = at0[1]; f.z = at0[2]; f.w = at0[3];
            *(float4*)&T2[n0 * HV_S + h0] = f;
            f.x = at1[0]; f.y = at1[1]; f.z = at1[2]; f.w = at1[3];
            *(float4*)&T2[n1 * HV_S + h0] = f;
            f.x = av0[0]; f.y = av0[1]; f.z = av0[2]; f.w = av0[3];
            *(float4*)&V2[n0 * HV_S + h0] = f;
            f.x = av1[0]; f.y = av1[1]; f.z = av1[2]; f.w = av1[3];
            *(float4*)&V2[n1 * HV_S + h0] = f;
        }
    }
    __syncthreads();

    // ---- P4a: U[n,h] = au + sum_j w'[n,j]*(T1+T2)[j,h]; combine V ----
    {
        const int pn = t & 15, ph0 = (t >> 4) * 4;
        float4 ua = *(const float4*)&U[pn * HV_S + ph0];
        float acc[4] = {ua.x, ua.y, ua.z, ua.w};
        #pragma unroll
        for (int j = 0; j < NN; j++) {
            float wv = w[pn * WT_S + j];
            float4 t1 = *(const float4*)&T1[j * HV_S + ph0];
            float4 t2 = *(const float4*)&T2[j * HV_S + ph0];
            acc[0] = fmaf(wv, t1.x, acc[0]); acc[0] = fmaf(wv, t2.x, acc[0]);
            acc[1] = fmaf(wv, t1.y, acc[1]); acc[1] = fmaf(wv, t2.y, acc[1]);
            acc[2] = fmaf(wv, t1.z, acc[2]); acc[2] = fmaf(wv, t2.z, acc[2]);
            acc[3] = fmaf(wv, t1.w, acc[3]); acc[3] = fmaf(wv, t2.w, acc[3]);
        }
        float4 uv; uv.x = acc[0]; uv.y = acc[1]; uv.z = acc[2]; uv.w = acc[3];
        *(float4*)&U[pn * HV_S + ph0] = uv;
        // combine V = V1 + V2 (each cell touched by exactly one thread)
        float4 v1 = *(const float4*)&V1[pn * HV_S + ph0];
        float4 v2 = *(const float4*)&V2[pn * HV_S + ph0];
        v1.x += v2.x; v1.y += v2.y; v1.z += v2.z; v1.w += v2.w;
        *(float4*)&V1[pn * HV_S + ph0] = v1;
    }
    __syncthreads();

    // ---- P4b: value[b,i,j] = W2 . lrelu(U[i] + w'[i,j]*V[j]) ----
    {
        const int i = t >> 4, j = t & 15;
        float wv = w[i * WT_S + j];    // scaled w/16 pairs with unscaled V
        float acc = 0.0f;
        #pragma unroll
        for (int h = 0; h < HH; h += 4) {
            float4 u4 = *(const float4*)&U[i * HV_S + h];
            float4 v4 = *(const float4*)&V1[j * HV_S + h];
            float4 w2 = *(const float4*)&W2s[h];
            acc = fmaf(w2.x, lrelu(fmaf(wv, v4.x, u4.x)), acc);
            acc = fmaf(w2.y, lrelu(fmaf(wv, v4.y, u4.y)), acc);
            acc = fmaf(w2.z, lrelu(fmaf(wv, v4.z, u4.z)), acc);
            acc = fmaf(w2.w, lrelu(fmaf(wv, v4.w, u4.w)), acc);
        }
        out[b * NN * NN + t] = acc;
    }
}

extern "C" void kernel_launch(void* const* d_in, const int* in_sizes, int n_in,
                              void* d_out, int out_size) {
    const float* st = (const float*)d_in[0];
    const float* po = (const float*)d_in[1];
    const float* ac = (const float*)d_in[2];
    const float* We = (const float*)d_in[3];
    const float* Wa = (const float*)d_in[4];
    const float* W1 = (const float*)d_in[5];
    const float* W2 = (const float*)d_in[6];
    float* out = (float*)d_out;

    const int smem = SMEM_FLOATS * (int)sizeof(float);
    cudaFuncSetAttribute(gac_kernel, cudaFuncAttributeMaxDynamicSharedMemorySize, smem);

    int write_w = (out_size >= 2 * BB * NN * NN) ? 1 : 0;

    gac_kernel<<<BB, 256, smem>>>(st, po, ac, We, Wa, W1, W2, out, write_w);
}